// round 1
// baseline (speedup 1.0000x reference)
#include <cuda_runtime.h>
#include <cuda_bf16.h>
#include <math.h>

#define BATCH 4096
#define P 256
#define FCH 20
#define HH 18
#define WW 18
#define HWSZ (HH*WW)          // 324
#define VOL (FCH*HWSZ)        // 6480
#define TB 16                 // batches per CTA in params kernel
#define PI_CONST 3.14159f

// Scratch: per (b,f): {scale, cos, sin, tx, ty}
__device__ float g_par[(size_t)BATCH * FCH * 5];

// ---------------------------------------------------------------------------
// Kernel 1: MLP head -> per-(b,f) affine params
// grid: BATCH/TB = 256 blocks, 256 threads
// ---------------------------------------------------------------------------
__global__ __launch_bounds__(256) void params_kernel(
    const float* __restrict__ pc,   // (B,P)
    const float* __restrict__ W1,   // (P,P)
    const float* __restrict__ b1,   // (P,)
    const float* __restrict__ Ws,   // (P,20)
    const float* __restrict__ bs,   // (20,)
    const float* __restrict__ Wr,   // (P,20)
    const float* __restrict__ br,   // (20,)
    const float* __restrict__ Wt,   // (P,40)
    const float* __restrict__ bt)   // (40,)
{
    __shared__ float pc_s[P][TB];       // transposed: [i][b], rows 64B-aligned
    __shared__ float h_s[TB][P + 1];    // padded to avoid bank aliasing

    const int tid = threadIdx.x;
    const int b0 = blockIdx.x * TB;

    // Load pc transposed (coalesced over tid)
    #pragma unroll
    for (int b = 0; b < TB; b++)
        pc_s[tid][b] = pc[(size_t)(b0 + b) * P + tid];
    __syncthreads();

    // GEMV: h[b][tid] = relu(sum_i pc[b][i] * W1[i][tid] + b1[tid])
    float acc[TB];
    #pragma unroll
    for (int b = 0; b < TB; b++) acc[b] = 0.f;

    #pragma unroll 4
    for (int i = 0; i < P; i++) {
        const float w = W1[i * P + tid];                  // coalesced
        const float4* prow = (const float4*)&pc_s[i][0];  // broadcast reads
        float4 p0 = prow[0], p1 = prow[1], p2 = prow[2], p3 = prow[3];
        acc[0]  = fmaf(p0.x, w, acc[0]);  acc[1]  = fmaf(p0.y, w, acc[1]);
        acc[2]  = fmaf(p0.z, w, acc[2]);  acc[3]  = fmaf(p0.w, w, acc[3]);
        acc[4]  = fmaf(p1.x, w, acc[4]);  acc[5]  = fmaf(p1.y, w, acc[5]);
        acc[6]  = fmaf(p1.z, w, acc[6]);  acc[7]  = fmaf(p1.w, w, acc[7]);
        acc[8]  = fmaf(p2.x, w, acc[8]);  acc[9]  = fmaf(p2.y, w, acc[9]);
        acc[10] = fmaf(p2.z, w, acc[10]); acc[11] = fmaf(p2.w, w, acc[11]);
        acc[12] = fmaf(p3.x, w, acc[12]); acc[13] = fmaf(p3.y, w, acc[13]);
        acc[14] = fmaf(p3.z, w, acc[14]); acc[15] = fmaf(p3.w, w, acc[15]);
    }

    const float bias = b1[tid];
    #pragma unroll
    for (int b = 0; b < TB; b++)
        h_s[b][tid] = fmaxf(acc[b] + bias, 0.f);
    __syncthreads();

    // Small heads: TB*80 = 1280 outputs, 5 per thread
    for (int o = tid; o < TB * 80; o += 256) {
        const int b = o / 80;
        const int col = o - b * 80;
        const float* hrow = h_s[b];
        float* dst = &g_par[(size_t)(b0 + b) * (FCH * 5)];

        if (col < 20) {
            float v = 0.f;
            #pragma unroll 8
            for (int i = 0; i < P; i++) v = fmaf(hrow[i], Ws[i * 20 + col], v);
            v += bs[col];
            const float scale = 2.f / (1.f + expf(-v));
            dst[col * 5 + 0] = scale;
        } else if (col < 40) {
            const int f = col - 20;
            float v = 0.f;
            #pragma unroll 8
            for (int i = 0; i < P; i++) v = fmaf(hrow[i], Wr[i * 20 + f], v);
            const float ang = tanhf(v + br[f]) * PI_CONST;
            dst[f * 5 + 1] = cosf(ang);
            dst[f * 5 + 2] = sinf(ang);
        } else {
            const int cc = col - 40;
            const int f = cc >> 1, ax = cc & 1;
            float v = 0.f;
            #pragma unroll 8
            for (int i = 0; i < P; i++) v = fmaf(hrow[i], Wt[i * 40 + cc], v);
            dst[f * 5 + 3 + ax] = tanhf(v + bt[cc]);
        }
    }
}

// ---------------------------------------------------------------------------
// Kernel 2: per-channel affine grid + trilinear sample (zeros padding,
// align_corners=False), volume staged in shared memory.
// grid: BATCH blocks, 256 threads
// ---------------------------------------------------------------------------
__global__ __launch_bounds__(256) void sample_kernel(
    const float* __restrict__ fm,   // (B,20,18,18)
    float* __restrict__ out)        // (B,20,18,18)
{
    __shared__ float fm_s[VOL];         // 25.9 KB
    __shared__ float par_s[FCH * 5];    // 100 floats

    const int b = blockIdx.x;
    const int tid = threadIdx.x;

    // Stage volume (float4: 6480 floats = 1620 float4)
    {
        const float4* src = (const float4*)(fm + (size_t)b * VOL);
        float4* dst = (float4*)fm_s;
        #pragma unroll 2
        for (int i = tid; i < VOL / 4; i += 256) dst[i] = src[i];
    }
    if (tid < FCH * 5) par_s[tid] = g_par[(size_t)b * (FCH * 5) + tid];
    __syncthreads();

    float* obase = out + (size_t)b * VOL;

    for (int idx = tid; idx < VOL; idx += 256) {
        const int f  = idx / HWSZ;
        const int p  = idx - f * HWSZ;
        const int py = p / WW;
        const int px = p - py * WW;

        const float gx = px * (2.f / 17.f) - 1.f;
        const float gy = py * (2.f / 17.f) - 1.f;

        const float* pp = &par_s[f * 5];
        const float scale = pp[0], c = pp[1], s = pp[2], tx = pp[3], ty = pp[4];

        const float tgx = (c * gx - s * gy) * scale + tx;
        const float tgy = (s * gx + c * gy) * scale + ty;

        // unnormalize (align_corners=False)
        const float ix = (tgx + 1.f) * 9.f - 0.5f;   // *W/2 - 0.5
        const float iy = (tgy + 1.f) * 9.f - 0.5f;   // *H/2 - 0.5
        const float iz = f * (20.f / 19.f) - 0.5f;   // z-grid is the identity coord

        const float x0f = floorf(ix), y0f = floorf(iy), z0f = floorf(iz);
        const float wx = ix - x0f, wy = iy - y0f, wz = iz - z0f;
        const int x0 = (int)x0f, y0 = (int)y0f, z0 = (int)z0f;

        float acc = 0.f;
        #pragma unroll
        for (int cz = 0; cz < 2; cz++) {
            const int z = z0 + cz;
            if ((unsigned)z < (unsigned)FCH) {
                const float wzz = cz ? wz : 1.f - wz;
                const float* plane = &fm_s[z * HWSZ];
                #pragma unroll
                for (int cy = 0; cy < 2; cy++) {
                    const int y = y0 + cy;
                    if ((unsigned)y < (unsigned)HH) {
                        const float wyy = cy ? wy : 1.f - wy;
                        const float wzy = wzz * wyy;
                        const float* row = &plane[y * WW];
                        #pragma unroll
                        for (int cx = 0; cx < 2; cx++) {
                            const int x = x0 + cx;
                            if ((unsigned)x < (unsigned)WW) {
                                const float wxx = cx ? wx : 1.f - wx;
                                acc = fmaf(wzy * wxx, row[x], acc);
                            }
                        }
                    }
                }
            }
        }
        obase[idx] = acc;
    }
}

// ---------------------------------------------------------------------------
extern "C" void kernel_launch(void* const* d_in, const int* in_sizes, int n_in,
                              void* d_out, int out_size)
{
    const float* feature_map = (const float*)d_in[0];
    const float* para_code   = (const float*)d_in[1];
    const float* W1 = (const float*)d_in[2];
    const float* b1 = (const float*)d_in[3];
    const float* Ws = (const float*)d_in[4];
    const float* bs = (const float*)d_in[5];
    const float* Wr = (const float*)d_in[6];
    const float* br = (const float*)d_in[7];
    const float* Wt = (const float*)d_in[8];
    const float* bt = (const float*)d_in[9];
    float* out = (float*)d_out;

    params_kernel<<<BATCH / TB, 256>>>(para_code, W1, b1, Ws, bs, Wr, br, Wt, bt);
    sample_kernel<<<BATCH, 256>>>(feature_map, out);
}

// round 2
// speedup vs baseline: 1.7433x; 1.7433x over previous
#include <cuda_runtime.h>
#include <cuda_bf16.h>
#include <math.h>

#define BATCH 4096
#define P 256
#define FCH 20
#define HH 18
#define WW 18
#define HWSZ (HH*WW)          // 324
#define VOL (FCH*HWSZ)        // 6480
#define TB 8                  // batches per CTA in params kernel
#define PI_CONST 3.14159f

// Scratch: per (b,f): {scale, cos, sin, tx, ty}
__device__ float g_par[(size_t)BATCH * FCH * 5];

// ---------------------------------------------------------------------------
// Kernel 1: MLP head -> per-(b,f) affine params
// grid: BATCH/TB = 512 blocks, 256 threads
// ---------------------------------------------------------------------------
__global__ __launch_bounds__(256) void params_kernel(
    const float* __restrict__ pc,   // (B,P)
    const float* __restrict__ W1,   // (P,P)
    const float* __restrict__ b1,   // (P,)
    const float* __restrict__ Ws,   // (P,20)
    const float* __restrict__ bs,   // (20,)
    const float* __restrict__ Wr,   // (P,20)
    const float* __restrict__ br,   // (20,)
    const float* __restrict__ Wt,   // (P,40)
    const float* __restrict__ bt)   // (40,)
{
    __shared__ float pc_s[P][TB];       // transposed: [i][b]
    __shared__ float h_s[TB][P + 1];    // padded

    const int tid = threadIdx.x;
    const int b0 = blockIdx.x * TB;

    // Load pc transposed (coalesced over tid)
    #pragma unroll
    for (int b = 0; b < TB; b++)
        pc_s[tid][b] = pc[(size_t)(b0 + b) * P + tid];
    __syncthreads();

    // GEMV: h[b][tid] = relu(sum_i pc[b][i] * W1[i][tid] + b1[tid])
    float acc[TB];
    #pragma unroll
    for (int b = 0; b < TB; b++) acc[b] = 0.f;

    #pragma unroll 4
    for (int i = 0; i < P; i++) {
        const float w = W1[i * P + tid];                  // coalesced
        const float4* prow = (const float4*)&pc_s[i][0];  // broadcast reads
        float4 p0 = prow[0], p1 = prow[1];
        acc[0] = fmaf(p0.x, w, acc[0]);  acc[1] = fmaf(p0.y, w, acc[1]);
        acc[2] = fmaf(p0.z, w, acc[2]);  acc[3] = fmaf(p0.w, w, acc[3]);
        acc[4] = fmaf(p1.x, w, acc[4]);  acc[5] = fmaf(p1.y, w, acc[5]);
        acc[6] = fmaf(p1.z, w, acc[6]);  acc[7] = fmaf(p1.w, w, acc[7]);
    }

    const float bias = b1[tid];
    #pragma unroll
    for (int b = 0; b < TB; b++)
        h_s[b][tid] = fmaxf(acc[b] + bias, 0.f);
    __syncthreads();

    // Small heads: TB*80 = 640 outputs
    for (int o = tid; o < TB * 80; o += 256) {
        const int b = o / 80;
        const int col = o - b * 80;
        const float* hrow = h_s[b];
        float* dst = &g_par[(size_t)(b0 + b) * (FCH * 5)];

        if (col < 20) {
            float v = 0.f;
            #pragma unroll 8
            for (int i = 0; i < P; i++) v = fmaf(hrow[i], Ws[i * 20 + col], v);
            v += bs[col];
            dst[col * 5 + 0] = 2.f / (1.f + expf(-v));
        } else if (col < 40) {
            const int f = col - 20;
            float v = 0.f;
            #pragma unroll 8
            for (int i = 0; i < P; i++) v = fmaf(hrow[i], Wr[i * 20 + f], v);
            const float ang = tanhf(v + br[f]) * PI_CONST;
            dst[f * 5 + 1] = cosf(ang);
            dst[f * 5 + 2] = sinf(ang);
        } else {
            const int cc = col - 40;
            const int f = cc >> 1, ax = cc & 1;
            float v = 0.f;
            #pragma unroll 8
            for (int i = 0; i < P; i++) v = fmaf(hrow[i], Wt[i * 40 + cc], v);
            dst[f * 5 + 3 + ax] = tanhf(v + bt[cc]);
        }
    }
}

// ---------------------------------------------------------------------------
// Kernel 2: z-preblended per-channel affine bilinear sample.
// grid: BATCH blocks, 352 threads (324 active)
// ---------------------------------------------------------------------------
__global__ __launch_bounds__(352) void sample_kernel(
    const float* __restrict__ fm,   // (B,20,18,18)
    float* __restrict__ out)        // (B,20,18,18)
{
    __shared__ float bl[FCH][HWSZ];     // z-blended planes, 25.9 KB
    __shared__ float par_s[FCH * 5];    // 100 floats

    const int b = blockIdx.x;
    const int tid = threadIdx.x;

    if (tid < FCH * 5) par_s[tid] = g_par[(size_t)b * (FCH * 5) + tid];

    const float* base = fm + (size_t)b * VOL;

    // Pre-blend z: bl[f][p] = w0*plane[z0][p] + w1*plane[z0+1][p]
    // (iz depends only on f; trilinear == bilinear on the blended plane)
    if (tid < HWSZ) {
        #pragma unroll
        for (int f = 0; f < FCH; f++) {
            const float iz = f * (20.f / 19.f) - 0.5f;
            const float z0f = floorf(iz);
            const float wz = iz - z0f;
            const int z0 = (int)z0f;
            float v0 = (z0 >= 0)      ? base[z0 * HWSZ + tid]       : 0.f;
            float v1 = (z0 + 1 < FCH) ? base[(z0 + 1) * HWSZ + tid] : 0.f;
            bl[f][tid] = (1.f - wz) * v0 + wz * v1;
        }
    }
    __syncthreads();

    if (tid < HWSZ) {
        const int py = tid / WW;
        const int px = tid - py * WW;
        const float gx = px * (2.f / 17.f) - 1.f;
        const float gy = py * (2.f / 17.f) - 1.f;
        float* ob = out + (size_t)b * VOL + tid;

        #pragma unroll 2
        for (int f = 0; f < FCH; f++) {
            const float* pp = &par_s[f * 5];
            const float scale = pp[0], c = pp[1], s = pp[2], tx = pp[3], ty = pp[4];

            const float tgx = (c * gx - s * gy) * scale + tx;
            const float tgy = (s * gx + c * gy) * scale + ty;

            // unnormalize (align_corners=False)
            const float ix = (tgx + 1.f) * 9.f - 0.5f;
            const float iy = (tgy + 1.f) * 9.f - 0.5f;

            const float x0f = floorf(ix), y0f = floorf(iy);
            const float wx = ix - x0f, wy = iy - y0f;
            const int x0 = (int)x0f, y0 = (int)y0f;
            const int x1 = x0 + 1, y1 = y0 + 1;

            // zero weights for OOB taps, clamp indices for safe LDS
            const float wxa = ((unsigned)x0 < (unsigned)WW) ? (1.f - wx) : 0.f;
            const float wxb = ((unsigned)x1 < (unsigned)WW) ? wx : 0.f;
            const float wya = ((unsigned)y0 < (unsigned)HH) ? (1.f - wy) : 0.f;
            const float wyb = ((unsigned)y1 < (unsigned)HH) ? wy : 0.f;

            const int xc0 = min(max(x0, 0), WW - 1);
            const int xc1 = min(max(x1, 0), WW - 1);
            const int ya = min(max(y0, 0), HH - 1) * WW;
            const int yb = min(max(y1, 0), HH - 1) * WW;

            const float* pl = bl[f];
            const float r0 = fmaf(wxa, pl[ya + xc0], wxb * pl[ya + xc1]);
            const float r1 = fmaf(wxa, pl[yb + xc0], wxb * pl[yb + xc1]);
            ob[f * HWSZ] = wya * r0 + wyb * r1;
        }
    }
}

// ---------------------------------------------------------------------------
extern "C" void kernel_launch(void* const* d_in, const int* in_sizes, int n_in,
                              void* d_out, int out_size)
{
    const float* feature_map = (const float*)d_in[0];
    const float* para_code   = (const float*)d_in[1];
    const float* W1 = (const float*)d_in[2];
    const float* b1 = (const float*)d_in[3];
    const float* Ws = (const float*)d_in[4];
    const float* bs = (const float*)d_in[5];
    const float* Wr = (const float*)d_in[6];
    const float* br = (const float*)d_in[7];
    const float* Wt = (const float*)d_in[8];
    const float* bt = (const float*)d_in[9];
    float* out = (float*)d_out;

    params_kernel<<<BATCH / TB, 256>>>(para_code, W1, b1, Ws, bs, Wr, br, Wt, bt);
    sample_kernel<<<BATCH, 352>>>(feature_map, out);
}